// round 1
// baseline (speedup 1.0000x reference)
#include <cuda_runtime.h>
#include <float.h>
#include <math.h>

#define B 128
#define N 512
#define C 7
#define H 64
#define KNN 16
#define R 2
#define EPS 1e-5f
#define NPTS (B*N)

// ---------------- scratch (static device arrays; no runtime allocation) ----------------
__device__ float g_hA[NPTS * H];   // 16 MB  features ping
__device__ float g_hB[NPTS * H];   // 16 MB  features pong
__device__ float g_a [NPTS * H];   // 16 MB  center-term  a = (Wa-Wb) h
__device__ float g_c [NPTS * H];   // 16 MB  neighbor-term c = Wb h
__device__ float g_sq[NPTS];       // 256 KB squared norms
__device__ int   g_idx[NPTS * KNN];// 4 MB   knn indices

// ---------------- stem: h = relu(bn(W2 relu(bn(W1 x)))) ----------------
// block: 256 threads, 64 points of one batch
__global__ __launch_bounds__(256) void k_stem(
    const float* __restrict__ x,
    const float* __restrict__ w1, const float* __restrict__ g1, const float* __restrict__ b1,
    const float* __restrict__ w2, const float* __restrict__ g2, const float* __restrict__ b2,
    float* __restrict__ out)
{
    __shared__ float xs[C * 64];      // [c][p]
    __shared__ float w1s[H * C];      // [o][c]
    __shared__ float w2t[H * 65];     // [c][o] padded
    __shared__ float h1s[64 * H];     // [p][o]

    int tid = threadIdx.x;
    int b   = blockIdx.x / (N / 64);
    int n0  = (blockIdx.x % (N / 64)) * 64;

    for (int i = tid; i < C * 64; i += 256)
        xs[i] = x[(size_t)b * C * N + (i >> 6) * N + n0 + (i & 63)];
    for (int i = tid; i < H * C; i += 256)
        w1s[i] = w1[i];
    for (int i = tid; i < H * H; i += 256) {
        int o = i >> 6, c = i & 63;
        w2t[c * 65 + o] = w2[i];
    }
    __syncthreads();

    const float inv = 1.0f / sqrtf(1.0f + EPS);

    #pragma unroll
    for (int i = 0; i < 16; i++) {
        int idx = tid + i * 256;          // 4096 = 64 pts * 64 ch
        int p = idx >> 6, o = idx & 63;
        float acc = 0.f;
        #pragma unroll
        for (int c = 0; c < C; c++) acc += w1s[o * C + c] * xs[c * 64 + p];
        float s = g1[o] * inv;
        h1s[idx] = fmaxf(acc * s + b1[o], 0.f);
    }
    __syncthreads();

    #pragma unroll
    for (int i = 0; i < 16; i++) {
        int idx = tid + i * 256;
        int p = idx >> 6, o = idx & 63;
        float acc = 0.f;
        #pragma unroll
        for (int c = 0; c < H; c++) acc += w2t[c * 65 + o] * h1s[p * 64 + c];
        float s = g2[o] * inv;
        out[((size_t)(b * N + n0)) * H + idx] = fmaxf(acc * s + b2[o], 0.f);
    }
}

// ---------------- squared norms ----------------
__global__ __launch_bounds__(256) void k_sq(const float* __restrict__ h, float* __restrict__ sq)
{
    int p    = blockIdx.x * 8 + (threadIdx.x >> 5);
    int lane = threadIdx.x & 31;
    float v0 = h[(size_t)p * H + lane];
    float v1 = h[(size_t)p * H + 32 + lane];
    float s  = v0 * v0 + v1 * v1;
    #pragma unroll
    for (int off = 16; off; off >>= 1) s += __shfl_xor_sync(0xffffffffu, s, off);
    if (lane == 0) sq[p] = s;
}

// ---------------- fused distance-GEMM + top-16 ----------------
// block: 256 threads (8 warps), 16 rows of one batch (2 rows per warp)
// lane's j slots: j = tile*128 + t*32 + lane, slot s = tile*4 + t  (all static after unroll)
__global__ __launch_bounds__(256) void k_knn(
    const float* __restrict__ h, const float* __restrict__ sq, int* __restrict__ idxout)
{
    __shared__ float his[16 * H];      // 4 KB
    __shared__ float hjs[128 * 65];    // 33.3 KB padded

    int b    = blockIdx.x / (N / 16);
    int i0   = (blockIdx.x % (N / 16)) * 16;
    int tid  = threadIdx.x;
    int lane = tid & 31;
    int warp = tid >> 5;               // 0..7
    int row0 = warp * 2;               // rows in block tile

    const float* hb = h + (size_t)b * N * H;

    for (int i = tid; i < 16 * H; i += 256)
        his[i] = hb[(size_t)i0 * H + i];

    float d[2][16];
    #pragma unroll
    for (int rr = 0; rr < 2; rr++)
        #pragma unroll
        for (int s = 0; s < 16; s++) d[rr][s] = 0.f;

    #pragma unroll
    for (int tile = 0; tile < 4; tile++) {
        __syncthreads();
        for (int i = tid; i < 128 * H; i += 256) {
            int j = i >> 6, c = i & 63;
            hjs[j * 65 + c] = hb[(size_t)(tile * 128 + j) * H + c];
        }
        __syncthreads();
        #pragma unroll 4
        for (int c = 0; c < H; c++) {
            float a0 = his[(row0 + 0) * 64 + c];
            float a1 = his[(row0 + 1) * 64 + c];
            #pragma unroll
            for (int t = 0; t < 4; t++) {
                float bv = hjs[(t * 32 + lane) * 65 + c];
                d[0][tile * 4 + t] += a0 * bv;
                d[1][tile * 4 + t] += a1 * bv;
            }
        }
    }

    // keys: sq_j - 2*dot   (sq_i constant per row -> ranking unchanged)
    #pragma unroll
    for (int s = 0; s < 16; s++) {
        int j = (s >> 2) * 128 + (s & 3) * 32 + lane;
        float sj = sq[(size_t)b * N + j];
        d[0][s] = sj - 2.f * d[0][s];
        d[1][s] = sj - 2.f * d[1][s];
    }

    // top-16 smallest by strict lexicographic (key, j) — no masking, no dynamic reg index
    #pragma unroll
    for (int rr = 0; rr < 2; rr++) {
        int rowg = i0 + row0 + rr;
        float pd = -FLT_MAX; int pj = -1;
        #pragma unroll 1
        for (int k = 0; k < KNN; k++) {
            float bd = FLT_MAX; int bj = 0x7fffffff;
            #pragma unroll
            for (int s = 0; s < 16; s++) {
                int j = (s >> 2) * 128 + (s & 3) * 32 + lane;
                float dv = d[rr][s];
                bool elig = (dv > pd) || (dv == pd && j > pj);
                if (elig && (dv < bd || (dv == bd && j < bj))) { bd = dv; bj = j; }
            }
            #pragma unroll
            for (int off = 16; off; off >>= 1) {
                float od = __shfl_xor_sync(0xffffffffu, bd, off);
                int   oj = __shfl_xor_sync(0xffffffffu, bj, off);
                if (od < bd || (od == bd && oj < bj)) { bd = od; bj = oj; }
            }
            if (lane == 0) idxout[(size_t)(b * N + rowg) * KNN + k] = bj;
            pd = bd; pj = bj;
        }
    }
}

// ---------------- a/c GEMMs: a = (Wa - Wb) h ; c = Wb h ----------------
// block: 256 threads, 32 points
__global__ __launch_bounds__(256) void k_ac(
    const float* __restrict__ h, const float* __restrict__ wnb,
    float* __restrict__ a, float* __restrict__ c)
{
    __shared__ float hs[32 * H];       // 8 KB
    __shared__ float wdt[H * 65];      // 16.6 KB  (Wa-Wb)^T
    __shared__ float w2t[H * 65];      // 16.6 KB  Wb^T

    int tid = threadIdx.x;
    int p0  = blockIdx.x * 32;

    for (int i = tid; i < 32 * H; i += 256)
        hs[i] = h[(size_t)p0 * H + i];
    for (int i = tid; i < H * H; i += 256) {
        int o = i >> 6, cc = i & 63;
        float wa = wnb[o * 128 + cc];
        float wb = wnb[o * 128 + 64 + cc];
        wdt[cc * 65 + o] = wa - wb;
        w2t[cc * 65 + o] = wb;
    }
    __syncthreads();

    #pragma unroll
    for (int i = 0; i < 8; i++) {
        int idx = tid + i * 256;       // 2048 = 32 pts * 64 ch
        int p = idx >> 6, o = idx & 63;
        float av = 0.f, cv = 0.f;
        #pragma unroll
        for (int cc = 0; cc < H; cc++) {
            float hv = hs[p * 64 + cc];
            av += wdt[cc * 65 + o] * hv;
            cv += w2t[cc * 65 + o] * hv;
        }
        a[(size_t)p0 * H + idx] = av;
        c[(size_t)p0 * H + idx] = cv;
    }
}

// ---------------- aggregate: h_out = relu(bn(a + extreme_j c_j)) ----------------
// warp per point; channelwise max (scale>=0) or min (scale<0) over the 16 neighbors
__global__ __launch_bounds__(256) void k_agg(
    const float* __restrict__ a, const float* __restrict__ c,
    const int* __restrict__ knn,
    const float* __restrict__ g, const float* __restrict__ bb,
    float* __restrict__ hout)
{
    int p    = blockIdx.x * 8 + (threadIdx.x >> 5);
    int lane = threadIdx.x & 31;
    int b    = p / N;
    const float* cb = c + (size_t)b * N * H;
    const int*   kn = knn + (size_t)p * KNN;

    float mx0 = -FLT_MAX, mx1 = -FLT_MAX, mn0 = FLT_MAX, mn1 = FLT_MAX;
    #pragma unroll
    for (int k = 0; k < KNN; k++) {
        int j = kn[k];
        float v0 = cb[(size_t)j * H + lane];
        float v1 = cb[(size_t)j * H + 32 + lane];
        mx0 = fmaxf(mx0, v0); mn0 = fminf(mn0, v0);
        mx1 = fmaxf(mx1, v1); mn1 = fminf(mn1, v1);
    }
    float a0 = a[(size_t)p * H + lane];
    float a1 = a[(size_t)p * H + 32 + lane];
    const float inv = 1.0f / sqrtf(1.0f + EPS);
    float s0 = g[lane] * inv, s1 = g[32 + lane] * inv;
    float e0 = (s0 >= 0.f) ? mx0 : mn0;
    float e1 = (s1 >= 0.f) ? mx1 : mn1;
    hout[(size_t)p * H + lane]      = fmaxf(s0 * (a0 + e0) + bb[lane],      0.f);
    hout[(size_t)p * H + 32 + lane] = fmaxf(s1 * (a1 + e1) + bb[32 + lane], 0.f);
}

// ---------------- head: logits = w_s2 . relu(bn(W_s1 h)) + b_s2 ----------------
// block: 256 threads, 32 points
__global__ __launch_bounds__(256) void k_head(
    const float* __restrict__ h,
    const float* __restrict__ ws1, const float* __restrict__ g1, const float* __restrict__ b1,
    const float* __restrict__ ws2, const float* __restrict__ b2,
    float* __restrict__ out)
{
    __shared__ float hs[32 * H];       // 8 KB
    __shared__ float w1t[H * 65];      // 16.6 KB
    __shared__ float ts[32 * H];       // 8 KB

    int tid = threadIdx.x;
    int p0  = blockIdx.x * 32;

    for (int i = tid; i < 32 * H; i += 256)
        hs[i] = h[(size_t)p0 * H + i];
    for (int i = tid; i < H * H; i += 256) {
        int o = i >> 6, cc = i & 63;
        w1t[cc * 65 + o] = ws1[i];
    }
    __syncthreads();

    const float inv = 1.0f / sqrtf(1.0f + EPS);

    #pragma unroll
    for (int i = 0; i < 8; i++) {
        int idx = tid + i * 256;
        int p = idx >> 6, o = idx & 63;
        float acc = 0.f;
        #pragma unroll
        for (int cc = 0; cc < H; cc++) acc += w1t[cc * 65 + o] * hs[p * 64 + cc];
        float s = g1[o] * inv;
        ts[idx] = fmaxf(acc * s + b1[o], 0.f);
    }
    __syncthreads();

    int lane = tid & 31, warp = tid >> 5;
    #pragma unroll
    for (int i = 0; i < 4; i++) {
        int pi = warp * 4 + i;
        float v = ts[pi * 64 + lane] * ws2[lane] + ts[pi * 64 + 32 + lane] * ws2[32 + lane];
        #pragma unroll
        for (int off = 16; off; off >>= 1) v += __shfl_xor_sync(0xffffffffu, v, off);
        if (lane == 0) out[p0 + pi] = v + b2[0];
    }
}

// ---------------- launch ----------------
extern "C" void kernel_launch(void* const* d_in, const int* in_sizes, int n_in,
                              void* d_out, int out_size)
{
    const float* x    = (const float*)d_in[0];
    const float* w_t1 = (const float*)d_in[1];
    const float* g_t1 = (const float*)d_in[2];
    const float* b_t1 = (const float*)d_in[3];
    const float* w_t2 = (const float*)d_in[4];
    const float* g_t2 = (const float*)d_in[5];
    const float* b_t2 = (const float*)d_in[6];
    const float* w_nb = (const float*)d_in[7];
    const float* g_nb = (const float*)d_in[8];
    const float* b_nb = (const float*)d_in[9];
    const float* w_s1 = (const float*)d_in[10];
    const float* g_s1 = (const float*)d_in[11];
    const float* b_s1 = (const float*)d_in[12];
    const float* w_s2 = (const float*)d_in[13];
    const float* b_s2 = (const float*)d_in[14];
    float* out = (float*)d_out;

    float *hA, *hB, *pa, *pc, *psq; int* pidx;
    cudaGetSymbolAddress((void**)&hA,  g_hA);
    cudaGetSymbolAddress((void**)&hB,  g_hB);
    cudaGetSymbolAddress((void**)&pa,  g_a);
    cudaGetSymbolAddress((void**)&pc,  g_c);
    cudaGetSymbolAddress((void**)&psq, g_sq);
    cudaGetSymbolAddress((void**)&pidx, g_idx);

    k_stem<<<B * (N / 64), 256>>>(x, w_t1, g_t1, b_t1, w_t2, g_t2, b_t2, hA);

    float* cur = hA;
    float* nxt = hB;
    for (int r = 0; r < R; r++) {
        k_sq <<<NPTS / 8,  256>>>(cur, psq);
        k_knn<<<B * (N / 16), 256>>>(cur, psq, pidx);
        k_ac <<<NPTS / 32, 256>>>(cur, w_nb + (size_t)r * H * 2 * H, pa, pc);
        k_agg<<<NPTS / 8,  256>>>(pa, pc, pidx, g_nb + r * H, b_nb + r * H, nxt);
        float* t = cur; cur = nxt; nxt = t;
    }

    k_head<<<NPTS / 32, 256>>>(cur, w_s1, g_s1, b_s1, w_s2, b_s2, out);
}

// round 3
// speedup vs baseline: 1.3594x; 1.3594x over previous
#include <cuda_runtime.h>
#include <float.h>
#include <math.h>

#define B 128
#define N 512
#define C 7
#define H 64
#define KNN 16
#define R 2
#define EPS 1e-5f
#define NPTS (B*N)

// ---------------- scratch ----------------
__device__ float g_hA[NPTS * H];
__device__ float g_hB[NPTS * H];
__device__ float g_a [NPTS * H];
__device__ float g_c [NPTS * H];
__device__ float g_sq[NPTS];
__device__ int   g_idx[NPTS * KNN];

// packed f32x2 FMA (sm_100+): d = a*b + d elementwise on packed pairs
#define FMA2(d,a,b) asm("fma.rn.f32x2 %0, %1, %2, %3;" : "=l"(d) : "l"(a), "l"(b), "l"(d))

__device__ __forceinline__ void unpack2(unsigned long long v, float& lo, float& hi) {
    asm("mov.b64 {%0,%1}, %2;" : "=f"(lo), "=f"(hi) : "l"(v));
}

// ============ stem: h = relu(bn(W2 relu(bn(W1 x)))), fused sq ============
// block 256 thr = 64 points; micro-tile 4p x 4o
__global__ __launch_bounds__(256,3) void k_stem(
    const float* __restrict__ x,
    const float* __restrict__ w1, const float* __restrict__ g1, const float* __restrict__ b1,
    const float* __restrict__ w2, const float* __restrict__ g2, const float* __restrict__ b2,
    float* __restrict__ out, float* __restrict__ sqout)
{
    __shared__ float xs [C * 68];     // [c][p]
    __shared__ float w1t[C * 68];     // [c][o]
    __shared__ float h1s[H * 68];     // [c2][p]  (= [o1][p])
    __shared__ float w2t[H * 68];     // [c][o]

    int tid = threadIdx.x;
    int b   = blockIdx.x >> 3;
    int n0  = (blockIdx.x & 7) << 6;

    for (int i = tid; i < C * 64; i += 256) {
        int c = i >> 6, p = i & 63;
        xs[c * 68 + p] = x[(size_t)b * C * N + c * N + n0 + p];
    }
    for (int i = tid; i < H * C; i += 256) {
        int o = i / 7, c = i - o * 7;
        w1t[c * 68 + o] = w1[i];
    }
    for (int i = tid; i < 1024; i += 256) {
        int o = i >> 4, c4 = (i & 15) << 2;
        float4 w = *(const float4*)&w2[o * 64 + c4];
        w2t[(c4+0) * 68 + o] = w.x; w2t[(c4+1) * 68 + o] = w.y;
        w2t[(c4+2) * 68 + o] = w.z; w2t[(c4+3) * 68 + o] = w.w;
    }
    __syncthreads();

    const float inv = 1.0f / sqrtf(1.0f + EPS);
    int po = (tid & 15) << 2, pp = (tid >> 4) << 2;

    // layer 1
    {
        float acc[16];
        #pragma unroll
        for (int i = 0; i < 16; i++) acc[i] = 0.f;
        #pragma unroll
        for (int c = 0; c < C; c++) {
            float4 hv = *(const float4*)&xs [c * 68 + pp];
            float4 wv = *(const float4*)&w1t[c * 68 + po];
            float hh[4] = {hv.x, hv.y, hv.z, hv.w};
            float ww[4] = {wv.x, wv.y, wv.z, wv.w};
            #pragma unroll
            for (int i = 0; i < 4; i++)
                #pragma unroll
                for (int j = 0; j < 4; j++) acc[i*4+j] += hh[i] * ww[j];
        }
        float4 gg = *(const float4*)&g1[po];
        float4 bb = *(const float4*)&b1[po];
        float gs[4] = {gg.x*inv, gg.y*inv, gg.z*inv, gg.w*inv};
        float bs[4] = {bb.x, bb.y, bb.z, bb.w};
        #pragma unroll
        for (int i = 0; i < 4; i++)
            #pragma unroll
            for (int j = 0; j < 4; j++)
                h1s[(po+j) * 68 + pp + i] = fmaxf(acc[i*4+j] * gs[j] + bs[j], 0.f);
    }
    __syncthreads();

    // layer 2
    {
        float acc[16];
        #pragma unroll
        for (int i = 0; i < 16; i++) acc[i] = 0.f;
        #pragma unroll 8
        for (int c = 0; c < H; c++) {
            float4 hv = *(const float4*)&h1s[c * 68 + pp];
            float4 wv = *(const float4*)&w2t[c * 68 + po];
            float hh[4] = {hv.x, hv.y, hv.z, hv.w};
            float ww[4] = {wv.x, wv.y, wv.z, wv.w};
            #pragma unroll
            for (int i = 0; i < 4; i++)
                #pragma unroll
                for (int j = 0; j < 4; j++) acc[i*4+j] += hh[i] * ww[j];
        }
        float4 gg = *(const float4*)&g2[po];
        float4 bb = *(const float4*)&b2[po];
        float gs[4] = {gg.x*inv, gg.y*inv, gg.z*inv, gg.w*inv};
        float bs[4] = {bb.x, bb.y, bb.z, bb.w};
        float sqv[4] = {0.f, 0.f, 0.f, 0.f};
        #pragma unroll
        for (int i = 0; i < 4; i++) {
            float v[4];
            #pragma unroll
            for (int j = 0; j < 4; j++) {
                v[j] = fmaxf(acc[i*4+j] * gs[j] + bs[j], 0.f);
                sqv[i] += v[j] * v[j];
            }
            float4 o4 = {v[0], v[1], v[2], v[3]};
            *(float4*)&out[((size_t)(b * N + n0 + pp + i)) * H + po] = o4;
        }
        #pragma unroll
        for (int i = 0; i < 4; i++) {
            #pragma unroll
            for (int off = 1; off < 16; off <<= 1)
                sqv[i] += __shfl_xor_sync(0xffffffffu, sqv[i], off);
        }
        if ((tid & 15) == 0) {
            #pragma unroll
            for (int i = 0; i < 4; i++)
                sqout[b * N + n0 + pp + i] = sqv[i];
        }
    }
}

// ============ fused distance-GEMM (f32x2) + exact top-16 ============
// block 256 thr (8 warps), 16 rows; warp = 2 rows, lane = 16 j-slots
__global__ __launch_bounds__(256,2) void k_knn(
    const float* __restrict__ h, const float* __restrict__ sq, int* __restrict__ idxout)
{
    __shared__ float his[16 * 64];     // 4 KB
    __shared__ float hjs[128 * 66];    // 33.8 KB (pad 66: conflict-free 64-bit LDS)
    __shared__ float sqs[512];         // 2 KB

    int b    = blockIdx.x >> 5;
    int i0   = (blockIdx.x & 31) << 4;
    int tid  = threadIdx.x;
    int lane = tid & 31;
    int warp = tid >> 5;
    int row0 = warp << 1;

    const float* hb = h + (size_t)b * N * H;

    for (int i = tid; i < 16 * 64; i += 256) his[i] = hb[(size_t)i0 * H + i];
    for (int i = tid; i < 512;     i += 256) sqs[i] = sq[b * N + i];

    unsigned long long acc[32];
    #pragma unroll
    for (int i = 0; i < 32; i++) acc[i] = 0ull;

    #pragma unroll
    for (int tile = 0; tile < 4; tile++) {
        __syncthreads();
        for (int i = tid; i < 128 * 32; i += 256) {
            int j = i >> 5, c2 = i & 31;
            *(float2*)&hjs[j * 66 + c2 * 2] =
                *(const float2*)&hb[(size_t)((tile << 7) + j) * 64 + c2 * 2];
        }
        __syncthreads();
        #pragma unroll 4
        for (int c2 = 0; c2 < 32; c2++) {
            unsigned long long a0 = *(const unsigned long long*)&his[(row0    ) * 64 + c2 * 2];
            unsigned long long a1 = *(const unsigned long long*)&his[(row0 + 1) * 64 + c2 * 2];
            #pragma unroll
            for (int t = 0; t < 4; t++) {
                unsigned long long bv = *(const unsigned long long*)&hjs[(t * 32 + lane) * 66 + c2 * 2];
                FMA2(acc[0 * 16 + tile * 4 + t], a0, bv);
                FMA2(acc[1 * 16 + tile * 4 + t], a1, bv);
            }
        }
    }

    // selection per row: u64 key = monotone(float) << 32 | j  (exact lex order)
    #pragma unroll
    for (int rr = 0; rr < 2; rr++) {
        unsigned long long s[16];
        #pragma unroll
        for (int t = 0; t < 16; t++) {
            float lo, hi; unpack2(acc[rr * 16 + t], lo, hi);
            int j = (((t >> 2)) << 7) + ((t & 3) << 5) + lane;
            float key = sqs[j] - 2.f * (lo + hi);
            unsigned u = __float_as_uint(key);
            u = (u & 0x80000000u) ? ~u : (u | 0x80000000u);
            s[t] = ((unsigned long long)u << 32) | (unsigned)j;
        }
        // bitonic sort 16 ascending (all indices static)
        #pragma unroll
        for (int kk = 2; kk <= 16; kk <<= 1) {
            #pragma unroll
            for (int jj = kk >> 1; jj > 0; jj >>= 1) {
                #pragma unroll
                for (int i = 0; i < 16; i++) {
                    int l = i ^ jj;
                    if (l > i) {
                        bool dir = ((i & kk) == 0);
                        unsigned long long x = s[i], y = s[l];
                        if ((x > y) == dir) { s[i] = y; s[l] = x; }
                    }
                }
            }
        }
        size_t rowbase = ((size_t)(b * N + i0 + row0 + rr)) * KNN;
        #pragma unroll 1
        for (int k = 0; k < KNN; k++) {
            unsigned long long w = s[0];
            #pragma unroll
            for (int off = 16; off; off >>= 1) {
                unsigned long long o = __shfl_xor_sync(0xffffffffu, w, off);
                if (o < w) w = o;
            }
            int wj = (int)(unsigned)w;
            if (lane == 0) idxout[rowbase + k] = wj;
            bool own = (lane == (wj & 31));
            #pragma unroll
            for (int i2 = 0; i2 < 15; i2++) s[i2] = own ? s[i2 + 1] : s[i2];
            s[15] = own ? 0xFFFFFFFFFFFFFFFFull : s[15];
        }
    }
}

// ============ a = (Wa-Wb) h ; c = Wb h  (two passes, shared wt buffer) ============
// block 256 thr = 64 points; micro-tile 4p x 4o
__global__ __launch_bounds__(256,3) void k_ac(
    const float* __restrict__ h, const float* __restrict__ wnb,
    float* __restrict__ a, float* __restrict__ c)
{
    __shared__ float hs[H * 68];   // [c][p]
    __shared__ float wt[H * 68];   // [c][o]

    int tid = threadIdx.x;
    int p0g = blockIdx.x << 6;

    for (int i = tid; i < 1024; i += 256) {
        int p = i >> 4, c4 = (i & 15) << 2;
        float4 v = *(const float4*)&h[(size_t)(p0g + p) * H + c4];
        hs[(c4+0) * 68 + p] = v.x; hs[(c4+1) * 68 + p] = v.y;
        hs[(c4+2) * 68 + p] = v.z; hs[(c4+3) * 68 + p] = v.w;
    }

    int po = (tid & 15) << 2, pp = (tid >> 4) << 2;

    #pragma unroll
    for (int m = 0; m < 2; m++) {
        __syncthreads();
        for (int i = tid; i < 1024; i += 256) {
            int o = i >> 4, c4 = (i & 15) << 2;
            float4 wb = *(const float4*)&wnb[o * 128 + 64 + c4];
            if (m == 0) {
                float4 wa = *(const float4*)&wnb[o * 128 + c4];
                wt[(c4+0) * 68 + o] = wa.x - wb.x; wt[(c4+1) * 68 + o] = wa.y - wb.y;
                wt[(c4+2) * 68 + o] = wa.z - wb.z; wt[(c4+3) * 68 + o] = wa.w - wb.w;
            } else {
                wt[(c4+0) * 68 + o] = wb.x; wt[(c4+1) * 68 + o] = wb.y;
                wt[(c4+2) * 68 + o] = wb.z; wt[(c4+3) * 68 + o] = wb.w;
            }
        }
        __syncthreads();

        float facc[16];
        #pragma unroll
        for (int i = 0; i < 16; i++) facc[i] = 0.f;
        #pragma unroll 8
        for (int cc = 0; cc < H; cc++) {
            float4 hv = *(const float4*)&hs[cc * 68 + pp];
            float4 wv = *(const float4*)&wt[cc * 68 + po];
            float hh[4] = {hv.x, hv.y, hv.z, hv.w};
            float ww[4] = {wv.x, wv.y, wv.z, wv.w};
            #pragma unroll
            for (int i = 0; i < 4; i++)
                #pragma unroll
                for (int j = 0; j < 4; j++) facc[i*4+j] += hh[i] * ww[j];
        }
        float* dst = (m == 0) ? a : c;
        #pragma unroll
        for (int i = 0; i < 4; i++) {
            float4 o4 = {facc[i*4+0], facc[i*4+1], facc[i*4+2], facc[i*4+3]};
            *(float4*)&dst[(size_t)(p0g + pp + i) * H + po] = o4;
        }
    }
}

// ============ aggregate + bn + relu + fused sq ============
// warp per point, float2 per lane
__global__ __launch_bounds__(256) void k_agg(
    const float* __restrict__ a, const float* __restrict__ c,
    const int* __restrict__ knn,
    const float* __restrict__ g, const float* __restrict__ bb,
    float* __restrict__ hout, float* __restrict__ sqout)
{
    int p    = blockIdx.x * 8 + (threadIdx.x >> 5);
    int lane = threadIdx.x & 31;
    int b    = p / N;
    const float2* cb = (const float2*)(c + (size_t)b * N * H);
    const int*    kn = knn + (size_t)p * KNN;

    float mx0 = -FLT_MAX, mx1 = -FLT_MAX, mn0 = FLT_MAX, mn1 = FLT_MAX;
    #pragma unroll
    for (int k = 0; k < KNN; k++) {
        int j = kn[k];
        float2 v = cb[(size_t)j * 32 + lane];
        mx0 = fmaxf(mx0, v.x); mn0 = fminf(mn0, v.x);
        mx1 = fmaxf(mx1, v.y); mn1 = fminf(mn1, v.y);
    }
    float2 av = ((const float2*)a)[(size_t)p * 32 + lane];
    float2 g2 = ((const float2*)g)[lane];
    float2 b2 = ((const float2*)bb)[lane];
    const float inv = 1.0f / sqrtf(1.0f + EPS);
    float s0 = g2.x * inv, s1 = g2.y * inv;
    float e0 = (s0 >= 0.f) ? mx0 : mn0;
    float e1 = (s1 >= 0.f) ? mx1 : mn1;
    float o0 = fmaxf(s0 * (av.x + e0) + b2.x, 0.f);
    float o1 = fmaxf(s1 * (av.y + e1) + b2.y, 0.f);
    float2 o2 = {o0, o1};
    ((float2*)hout)[(size_t)p * 32 + lane] = o2;

    float sv = o0 * o0 + o1 * o1;
    #pragma unroll
    for (int off = 16; off; off >>= 1) sv += __shfl_xor_sync(0xffffffffu, sv, off);
    if (lane == 0) sqout[p] = sv;
}

// ============ head: logits = ws2 . relu(bn(Ws1 h)) + b2 ============
// block 256 thr = 64 points; ts reuses hs buffer
__global__ __launch_bounds__(256,3) void k_head(
    const float* __restrict__ h,
    const float* __restrict__ ws1, const float* __restrict__ g1, const float* __restrict__ b1,
    const float* __restrict__ ws2, const float* __restrict__ b2,
    float* __restrict__ out)
{
    __shared__ float hs[H * 68];   // [c][p], later reused as ts [p][o]
    __shared__ float wt[H * 68];   // [c][o]

    int tid = threadIdx.x;
    int p0g = blockIdx.x << 6;

    for (int i = tid; i < 1024; i += 256) {
        int p = i >> 4, c4 = (i & 15) << 2;
        float4 v = *(const float4*)&h[(size_t)(p0g + p) * H + c4];
        hs[(c4+0) * 68 + p] = v.x; hs[(c4+1) * 68 + p] = v.y;
        hs[(c4+2) * 68 + p] = v.z; hs[(c4+3) * 68 + p] = v.w;
    }
    for (int i = tid; i < 1024; i += 256) {
        int o = i >> 4, c4 = (i & 15) << 2;
        float4 w = *(const float4*)&ws1[o * 64 + c4];
        wt[(c4+0) * 68 + o] = w.x; wt[(c4+1) * 68 + o] = w.y;
        wt[(c4+2) * 68 + o] = w.z; wt[(c4+3) * 68 + o] = w.w;
    }
    __syncthreads();

    const float inv = 1.0f / sqrtf(1.0f + EPS);
    int po = (tid & 15) << 2, pp = (tid >> 4) << 2;

    float acc[16];
    #pragma unroll
    for (int i = 0; i < 16; i++) acc[i] = 0.f;
    #pragma unroll 8
    for (int cc = 0; cc < H; cc++) {
        float4 hv = *(const float4*)&hs[cc * 68 + pp];
        float4 wv = *(const float4*)&wt[cc * 68 + po];
        float hh[4] = {hv.x, hv.y, hv.z, hv.w};
        float ww[4] = {wv.x, wv.y, wv.z, wv.w};
        #pragma unroll
        for (int i = 0; i < 4; i++)
            #pragma unroll
            for (int j = 0; j < 4; j++) acc[i*4+j] += hh[i] * ww[j];
    }
    float4 gg = *(const float4*)&g1[po];
    float4 bv = *(const float4*)&b1[po];
    float gs[4] = {gg.x*inv, gg.y*inv, gg.z*inv, gg.w*inv};
    float bs[4] = {bv.x, bv.y, bv.z, bv.w};
    __syncthreads();                 // all reads of hs done -> safe to reuse as ts
    #pragma unroll
    for (int i = 0; i < 4; i++)
        #pragma unroll
        for (int j = 0; j < 4; j++)
            hs[(pp + i) * 68 + po + j] = fmaxf(acc[i*4+j] * gs[j] + bs[j], 0.f);
    __syncthreads();

    int lane = tid & 31, warp = tid >> 5;
    float w0 = ws2[lane], w1 = ws2[32 + lane];
    #pragma unroll
    for (int i = 0; i < 8; i++) {
        int pi = warp * 8 + i;
        float v = hs[pi * 68 + lane] * w0 + hs[pi * 68 + 32 + lane] * w1;
        #pragma unroll
        for (int off = 16; off; off >>= 1) v += __shfl_xor_sync(0xffffffffu, v, off);
        if (lane == 0) out[p0g + pi] = v + b2[0];
    }
}

// ---------------- launch ----------------
extern "C" void kernel_launch(void* const* d_in, const int* in_sizes, int n_in,
                              void* d_out, int out_size)
{
    const float* x    = (const float*)d_in[0];
    const float* w_t1 = (const float*)d_in[1];
    const float* g_t1 = (const float*)d_in[2];
    const float* b_t1 = (const float*)d_in[3];
    const float* w_t2 = (const float*)d_in[4];
    const float* g_t2 = (const float*)d_in[5];
    const float* b_t2 = (const float*)d_in[6];
    const float* w_nb = (const float*)d_in[7];
    const float* g_nb = (const float*)d_in[8];
    const float* b_nb = (const float*)d_in[9];
    const float* w_s1 = (const float*)d_in[10];
    const float* g_s1 = (const float*)d_in[11];
    const float* b_s1 = (const float*)d_in[12];
    const float* w_s2 = (const float*)d_in[13];
    const float* b_s2 = (const float*)d_in[14];
    float* out = (float*)d_out;

    float *hA, *hB, *pa, *pc, *psq; int* pidx;
    cudaGetSymbolAddress((void**)&hA,  g_hA);
    cudaGetSymbolAddress((void**)&hB,  g_hB);
    cudaGetSymbolAddress((void**)&pa,  g_a);
    cudaGetSymbolAddress((void**)&pc,  g_c);
    cudaGetSymbolAddress((void**)&psq, g_sq);
    cudaGetSymbolAddress((void**)&pidx, g_idx);

    k_stem<<<B * (N / 64), 256>>>(x, w_t1, g_t1, b_t1, w_t2, g_t2, b_t2, hA, psq);

    float* cur = hA;
    float* nxt = hB;
    for (int r = 0; r < R; r++) {
        k_knn<<<B * (N / 16), 256>>>(cur, psq, pidx);
        k_ac <<<NPTS / 64, 256>>>(cur, w_nb + (size_t)r * H * 2 * H, pa, pc);
        k_agg<<<NPTS / 8,  256>>>(pa, pc, pidx, g_nb + r * H, b_nb + r * H, nxt, psq);
        float* t = cur; cur = nxt; nxt = t;
    }

    k_head<<<NPTS / 64, 256>>>(cur, w_s1, g_s1, b_s1, w_s2, b_s2, out);
}

// round 6
// speedup vs baseline: 1.5687x; 1.1540x over previous
#include <cuda_runtime.h>
#include <float.h>
#include <math.h>

#define B 128
#define N 512
#define C 7
#define H 64
#define KNN 16
#define R 2
#define EPS 1e-5f
#define NPTS (B*N)

typedef unsigned long long u64;
typedef unsigned int u32;

// ---------------- scratch ----------------
__device__ float g_hA[NPTS * H];
__device__ float g_hB[NPTS * H];
__device__ float g_a [NPTS * H];
__device__ float g_c [NPTS * H];
__device__ float g_sq[NPTS];
__device__ int   g_idx[NPTS * KNN];

// packed f32x2 FMA (sm_100+): d = a*b + d elementwise on packed pairs
#define FMA2(d,a,b) asm("fma.rn.f32x2 %0, %1, %2, %3;" : "=l"(d) : "l"(a), "l"(b), "l"(d))

__device__ __forceinline__ void unpack2(u64 v, float& lo, float& hi) {
    asm("mov.b64 {%0,%1}, %2;" : "=f"(lo), "=f"(hi) : "l"(v));
}
__device__ __forceinline__ u64 pack2(float x, float y) {
    u64 r; asm("mov.b64 %0, {%1,%2};" : "=l"(r) : "f"(x), "f"(y)); return r;
}

// ============ stem: h = relu(bn(W2 relu(bn(W1 x)))), fused sq ============
__global__ __launch_bounds__(256,3) void k_stem(
    const float* __restrict__ x,
    const float* __restrict__ w1, const float* __restrict__ g1, const float* __restrict__ b1,
    const float* __restrict__ w2, const float* __restrict__ g2, const float* __restrict__ b2,
    float* __restrict__ out, float* __restrict__ sqout)
{
    __shared__ float xs [C * 68];
    __shared__ float w1t[C * 68];
    __shared__ float h1s[H * 68];
    __shared__ float w2t[H * 68];

    int tid = threadIdx.x;
    int b   = blockIdx.x >> 3;
    int n0  = (blockIdx.x & 7) << 6;

    for (int i = tid; i < C * 64; i += 256) {
        int c = i >> 6, p = i & 63;
        xs[c * 68 + p] = x[(size_t)b * C * N + c * N + n0 + p];
    }
    for (int i = tid; i < H * C; i += 256) {
        int o = i / 7, c = i - o * 7;
        w1t[c * 68 + o] = w1[i];
    }
    for (int i = tid; i < 1024; i += 256) {
        int o = i >> 4, c4 = (i & 15) << 2;
        float4 w = *(const float4*)&w2[o * 64 + c4];
        w2t[(c4+0) * 68 + o] = w.x; w2t[(c4+1) * 68 + o] = w.y;
        w2t[(c4+2) * 68 + o] = w.z; w2t[(c4+3) * 68 + o] = w.w;
    }
    __syncthreads();

    const float inv = 1.0f / sqrtf(1.0f + EPS);
    int po = (tid & 15) << 2, pp = (tid >> 4) << 2;

    {
        float acc[16];
        #pragma unroll
        for (int i = 0; i < 16; i++) acc[i] = 0.f;
        #pragma unroll
        for (int c = 0; c < C; c++) {
            float4 hv = *(const float4*)&xs [c * 68 + pp];
            float4 wv = *(const float4*)&w1t[c * 68 + po];
            float hh[4] = {hv.x, hv.y, hv.z, hv.w};
            float ww[4] = {wv.x, wv.y, wv.z, wv.w};
            #pragma unroll
            for (int i = 0; i < 4; i++)
                #pragma unroll
                for (int j = 0; j < 4; j++) acc[i*4+j] += hh[i] * ww[j];
        }
        float4 gg = *(const float4*)&g1[po];
        float4 bb = *(const float4*)&b1[po];
        float gs[4] = {gg.x*inv, gg.y*inv, gg.z*inv, gg.w*inv};
        float bs[4] = {bb.x, bb.y, bb.z, bb.w};
        #pragma unroll
        for (int i = 0; i < 4; i++)
            #pragma unroll
            for (int j = 0; j < 4; j++)
                h1s[(po+j) * 68 + pp + i] = fmaxf(acc[i*4+j] * gs[j] + bs[j], 0.f);
    }
    __syncthreads();

    {
        float acc[16];
        #pragma unroll
        for (int i = 0; i < 16; i++) acc[i] = 0.f;
        #pragma unroll 8
        for (int c = 0; c < H; c++) {
            float4 hv = *(const float4*)&h1s[c * 68 + pp];
            float4 wv = *(const float4*)&w2t[c * 68 + po];
            float hh[4] = {hv.x, hv.y, hv.z, hv.w};
            float ww[4] = {wv.x, wv.y, wv.z, wv.w};
            #pragma unroll
            for (int i = 0; i < 4; i++)
                #pragma unroll
                for (int j = 0; j < 4; j++) acc[i*4+j] += hh[i] * ww[j];
        }
        float4 gg = *(const float4*)&g2[po];
        float4 bb = *(const float4*)&b2[po];
        float gs[4] = {gg.x*inv, gg.y*inv, gg.z*inv, gg.w*inv};
        float bs[4] = {bb.x, bb.y, bb.z, bb.w};
        float sqv[4] = {0.f, 0.f, 0.f, 0.f};
        #pragma unroll
        for (int i = 0; i < 4; i++) {
            float v[4];
            #pragma unroll
            for (int j = 0; j < 4; j++) {
                v[j] = fmaxf(acc[i*4+j] * gs[j] + bs[j], 0.f);
                sqv[i] += v[j] * v[j];
            }
            float4 o4 = {v[0], v[1], v[2], v[3]};
            *(float4*)&out[((size_t)(b * N + n0 + pp + i)) * H + po] = o4;
        }
        #pragma unroll
        for (int i = 0; i < 4; i++) {
            #pragma unroll
            for (int off = 1; off < 16; off <<= 1)
                sqv[i] += __shfl_xor_sync(0xffffffffu, sqv[i], off);
        }
        if ((tid & 15) == 0) {
            #pragma unroll
            for (int i = 0; i < 4; i++)
                sqout[b * N + n0 + pp + i] = sqv[i];
        }
    }
}

// ============ fused distance-GEMM (f32x2, float4-swizzled smem) + exact top-16 ============
// block 256 thr (8 warps), 16 rows; warp = 2 rows, lane = 16 j-slots
__global__ __launch_bounds__(256,2) void k_knn(
    const float* __restrict__ h, const float* __restrict__ sq, int* __restrict__ idxout)
{
    __shared__ float his[16 * 64];     // 4 KB
    __shared__ u64   hjsU[4096];       // 32 KB; GEMM tile (as float4) then selection spill
    __shared__ float sqs[512];         // 2 KB

    int b    = blockIdx.x >> 5;
    int i0   = (blockIdx.x & 31) << 4;
    int tid  = threadIdx.x;
    int lane = tid & 31;
    int warp = tid >> 5;
    int row0 = warp << 1;
    int lmask = lane & 15;

    const float* hb = h + (size_t)b * N * H;
    float4* hjsF = (float4*)hjsU;      // 2048 float4 = 128 rows x 16 chunks

    for (int i = tid; i < 16 * 64; i += 256) his[i] = hb[(size_t)i0 * H + i];
    for (int i = tid; i < 512;     i += 256) sqs[i] = sq[b * N + i];

    u64 acc[32];
    #pragma unroll
    for (int i = 0; i < 32; i++) acc[i] = 0ull;

    #pragma unroll
    for (int tile = 0; tile < 4; tile++) {
        __syncthreads();
        // fill swizzled at float4 granularity: chunk q of row j at column (q ^ (j&15))
        for (int i = tid; i < 128 * 16; i += 256) {
            int j = i >> 4, q = i & 15;
            float4 v = *(const float4*)&hb[(size_t)((tile << 7) + j) * 64 + q * 4];
            hjsF[j * 16 + (q ^ (j & 15))] = v;
        }
        __syncthreads();
        #pragma unroll 4
        for (int q = 0; q < 16; q++) {
            float4 av0 = *(const float4*)&his[(row0    ) * 64 + q * 4];
            float4 av1 = *(const float4*)&his[(row0 + 1) * 64 + q * 4];
            u64 a0lo = pack2(av0.x, av0.y), a0hi = pack2(av0.z, av0.w);
            u64 a1lo = pack2(av1.x, av1.y), a1hi = pack2(av1.z, av1.w);
            int qx = q ^ lmask;
            #pragma unroll
            for (int t = 0; t < 4; t++) {
                float4 bv = hjsF[(t * 32 + lane) * 16 + qx];
                u64 blo = pack2(bv.x, bv.y), bhi = pack2(bv.z, bv.w);
                FMA2(acc[     tile * 4 + t], a0lo, blo);
                FMA2(acc[     tile * 4 + t], a0hi, bhi);
                FMA2(acc[16 + tile * 4 + t], a1lo, blo);
                FMA2(acc[16 + tile * 4 + t], a1hi, bhi);
            }
        }
    }
    __syncthreads();   // all hjs GEMM reads done before selection reuses the buffer

    u64* sreg = hjsU + (warp << 9);    // 512 u64 per warp

    #pragma unroll
    for (int rr = 0; rr < 2; rr++) {
        u64 s[16];
        #pragma unroll
        for (int t = 0; t < 16; t++) {
            float lo, hi; unpack2(acc[rr * 16 + t], lo, hi);
            int j = ((t >> 2) << 7) + ((t & 3) << 5) + lane;
            float key = sqs[j] - 2.f * (lo + hi);
            u32 u = __float_as_uint(key);
            u = (u & 0x80000000u) ? ~u : (u | 0x80000000u);
            s[t] = ((u64)u << 32) | (u32)j;
        }
        // bitonic sort 16 ascending (static indices)
        #pragma unroll
        for (int kk = 2; kk <= 16; kk <<= 1) {
            #pragma unroll
            for (int jj = kk >> 1; jj > 0; jj >>= 1) {
                #pragma unroll
                for (int i = 0; i < 16; i++) {
                    int l = i ^ jj;
                    if (l > i) {
                        bool dir = ((i & kk) == 0);
                        u64 x = s[i], y = s[l];
                        if ((x > y) == dir) { s[i] = y; s[l] = x; }
                    }
                }
            }
        }
        // spill sorted lists transposed: bank = lane -> conflict-free at any head
        #pragma unroll
        for (int i = 0; i < 16; i++) sreg[i * 32 + lane] = s[i];
        __syncwarp();

        size_t rowbase = ((size_t)(b * N + i0 + row0 + rr)) * KNN;
        u32 khi = (u32)(s[0] >> 32);
        u32 klo = (u32)s[0];
        int hidx = 0;
        #pragma unroll 1
        for (int k = 0; k < KNN; k++) {
            u32 mh = __reduce_min_sync(0xffffffffu, khi);
            u32 cand = (khi == mh) ? klo : 0xffffffffu;
            u32 mj = __reduce_min_sync(0xffffffffu, cand);
            if (lane == 0) idxout[rowbase + k] = (int)mj;
            bool own = (khi == mh) && (klo == mj);
            hidx += own;
            int hc = hidx < 15 ? hidx : 15;
            u64 nv = sreg[hc * 32 + lane];
            if (own) {
                if (hidx < 16) { khi = (u32)(nv >> 32); klo = (u32)nv; }
                else           { khi = 0xffffffffu;     klo = 0xffffffffu; }
            }
        }
        __syncwarp();
    }
}

// ============ a = (Wa-Wb) h ; c = Wb h ============
__global__ __launch_bounds__(256,3) void k_ac(
    const float* __restrict__ h, const float* __restrict__ wnb,
    float* __restrict__ a, float* __restrict__ c)
{
    __shared__ float hs[H * 68];
    __shared__ float wt[H * 68];

    int tid = threadIdx.x;
    int p0g = blockIdx.x << 6;

    for (int i = tid; i < 1024; i += 256) {
        int p = i >> 4, c4 = (i & 15) << 2;
        float4 v = *(const float4*)&h[(size_t)(p0g + p) * H + c4];
        hs[(c4+0) * 68 + p] = v.x; hs[(c4+1) * 68 + p] = v.y;
        hs[(c4+2) * 68 + p] = v.z; hs[(c4+3) * 68 + p] = v.w;
    }

    int po = (tid & 15) << 2, pp = (tid >> 4) << 2;

    #pragma unroll
    for (int m = 0; m < 2; m++) {
        __syncthreads();
        for (int i = tid; i < 1024; i += 256) {
            int o = i >> 4, c4 = (i & 15) << 2;
            float4 wb = *(const float4*)&wnb[o * 128 + 64 + c4];
            if (m == 0) {
                float4 wa = *(const float4*)&wnb[o * 128 + c4];
                wt[(c4+0) * 68 + o] = wa.x - wb.x; wt[(c4+1) * 68 + o] = wa.y - wb.y;
                wt[(c4+2) * 68 + o] = wa.z - wb.z; wt[(c4+3) * 68 + o] = wa.w - wb.w;
            } else {
                wt[(c4+0) * 68 + o] = wb.x; wt[(c4+1) * 68 + o] = wb.y;
                wt[(c4+2) * 68 + o] = wb.z; wt[(c4+3) * 68 + o] = wb.w;
            }
        }
        __syncthreads();

        float facc[16];
        #pragma unroll
        for (int i = 0; i < 16; i++) facc[i] = 0.f;
        #pragma unroll 8
        for (int cc = 0; cc < H; cc++) {
            float4 hv = *(const float4*)&hs[cc * 68 + pp];
            float4 wv = *(const float4*)&wt[cc * 68 + po];
            float hh[4] = {hv.x, hv.y, hv.z, hv.w};
            float ww[4] = {wv.x, wv.y, wv.z, wv.w};
            #pragma unroll
            for (int i = 0; i < 4; i++)
                #pragma unroll
                for (int j = 0; j < 4; j++) facc[i*4+j] += hh[i] * ww[j];
        }
        float* dst = (m == 0) ? a : c;
        #pragma unroll
        for (int i = 0; i < 4; i++) {
            float4 o4 = {facc[i*4+0], facc[i*4+1], facc[i*4+2], facc[i*4+3]};
            *(float4*)&dst[(size_t)(p0g + pp + i) * H + po] = o4;
        }
    }
}

// ============ aggregate + bn + relu + fused sq ============
__global__ __launch_bounds__(256) void k_agg(
    const float* __restrict__ a, const float* __restrict__ c,
    const int* __restrict__ knn,
    const float* __restrict__ g, const float* __restrict__ bb,
    float* __restrict__ hout, float* __restrict__ sqout)
{
    int p    = blockIdx.x * 8 + (threadIdx.x >> 5);
    int lane = threadIdx.x & 31;
    int b    = p / N;
    const float2* cb = (const float2*)(c + (size_t)b * N * H);
    const int*    kn = knn + (size_t)p * KNN;

    float mx0 = -FLT_MAX, mx1 = -FLT_MAX, mn0 = FLT_MAX, mn1 = FLT_MAX;
    #pragma unroll
    for (int k = 0; k < KNN; k++) {
        int j = kn[k];
        float2 v = cb[(size_t)j * 32 + lane];
        mx0 = fmaxf(mx0, v.x); mn0 = fminf(mn0, v.x);
        mx1 = fmaxf(mx1, v.y); mn1 = fminf(mn1, v.y);
    }
    float2 av = ((const float2*)a)[(size_t)p * 32 + lane];
    float2 g2 = ((const float2*)g)[lane];
    float2 b2 = ((const float2*)bb)[lane];
    const float inv = 1.0f / sqrtf(1.0f + EPS);
    float s0 = g2.x * inv, s1 = g2.y * inv;
    float e0 = (s0 >= 0.f) ? mx0 : mn0;
    float e1 = (s1 >= 0.f) ? mx1 : mn1;
    float o0 = fmaxf(s0 * (av.x + e0) + b2.x, 0.f);
    float o1 = fmaxf(s1 * (av.y + e1) + b2.y, 0.f);
    float2 o2 = {o0, o1};
    ((float2*)hout)[(size_t)p * 32 + lane] = o2;

    float sv = o0 * o0 + o1 * o1;
    #pragma unroll
    for (int off = 16; off; off >>= 1) sv += __shfl_xor_sync(0xffffffffu, sv, off);
    if (lane == 0) sqout[p] = sv;
}

// ============ head ============
__global__ __launch_bounds__(256,3) void k_head(
    const float* __restrict__ h,
    const float* __restrict__ ws1, const float* __restrict__ g1, const float* __restrict__ b1,
    const float* __restrict__ ws2, const float* __restrict__ b2,
    float* __restrict__ out)
{
    __shared__ float hs[H * 68];
    __shared__ float wt[H * 68];

    int tid = threadIdx.x;
    int p0g = blockIdx.x << 6;

    for (int i = tid; i < 1024; i += 256) {
        int p = i >> 4, c4 = (i & 15) << 2;
        float4 v = *(const float4*)&h[(size_t)(p0g + p) * H + c4];
        hs[(c4+0) * 68 + p] = v.x; hs[(c4+1) * 68 + p] = v.y;
        hs[(c4+2) * 68 + p] = v.z; hs[(c4+3) * 68 + p] = v.w;
    }
    for (int i = tid; i < 1024; i += 256) {
        int o = i >> 4, c4 = (i & 15) << 2;
        float4 w = *(const float4*)&ws1[o * 64 + c4];
        wt[(c4+0) * 68 + o] = w.x; wt[(c4+1) * 68 + o] = w.y;
        wt[(c4+2) * 68 + o] = w.z; wt[(c4+3) * 68 + o] = w.w;
    }
    __syncthreads();

    const float inv = 1.0f / sqrtf(1.0f + EPS);
    int po = (tid & 15) << 2, pp = (tid >> 4) << 2;

    float acc[16];
    #pragma unroll
    for (int i = 0; i < 16; i++) acc[i] = 0.f;
    #pragma unroll 8
    for (int cc = 0; cc < H; cc++) {
        float4 hv = *(const float4*)&hs[cc * 68 + pp];
        float4 wv = *(const float4*)&wt[cc * 68 + po];
        float hh[4] = {hv.x, hv.y, hv.z, hv.w};
        float ww[4] = {wv.x, wv.y, wv.z, wv.w};
        #pragma unroll
        for (int i = 0; i < 4; i++)
            #pragma unroll
            for (int j = 0; j < 4; j++) acc[i*4+j] += hh[i] * ww[j];
    }
    float4 gg = *(const float4*)&g1[po];
    float4 bv = *(const float4*)&b1[po];
    float gs[4] = {gg.x*inv, gg.y*inv, gg.z*inv, gg.w*inv};
    float bs[4] = {bv.x, bv.y, bv.z, bv.w};
    __syncthreads();
    #pragma unroll
    for (int i = 0; i < 4; i++)
        #pragma unroll
        for (int j = 0; j < 4; j++)
            hs[(pp + i) * 68 + po + j] = fmaxf(acc[i*4+j] * gs[j] + bs[j], 0.f);
    __syncthreads();

    int lane = tid & 31, warp = tid >> 5;
    float w0 = ws2[lane], w1 = ws2[32 + lane];
    #pragma unroll
    for (int i = 0; i < 8; i++) {
        int pi = warp * 8 + i;
        float v = hs[pi * 68 + lane] * w0 + hs[pi * 68 + 32 + lane] * w1;
        #pragma unroll
        for (int off = 16; off; off >>= 1) v += __shfl_xor_sync(0xffffffffu, v, off);
        if (lane == 0) out[p0g + pi] = v + b2[0];
    }
}

// ---------------- launch ----------------
extern "C" void kernel_launch(void* const* d_in, const int* in_sizes, int n_in,
                              void* d_out, int out_size)
{
    const float* x    = (const float*)d_in[0];
    const float* w_t1 = (const float*)d_in[1];
    const float* g_t1 = (const float*)d_in[2];
    const float* b_t1 = (const float*)d_in[3];
    const float* w_t2 = (const float*)d_in[4];
    const float* g_t2 = (const float*)d_in[5];
    const float* b_t2 = (const float*)d_in[6];
    const float* w_nb = (const float*)d_in[7];
    const float* g_nb = (const float*)d_in[8];
    const float* b_nb = (const float*)d_in[9];
    const float* w_s1 = (const float*)d_in[10];
    const float* g_s1 = (const float*)d_in[11];
    const float* b_s1 = (const float*)d_in[12];
    const float* w_s2 = (const float*)d_in[13];
    const float* b_s2 = (const float*)d_in[14];
    float* out = (float*)d_out;

    float *hA, *hB, *pa, *pc, *psq; int* pidx;
    cudaGetSymbolAddress((void**)&hA,  g_hA);
    cudaGetSymbolAddress((void**)&hB,  g_hB);
    cudaGetSymbolAddress((void**)&pa,  g_a);
    cudaGetSymbolAddress((void**)&pc,  g_c);
    cudaGetSymbolAddress((void**)&psq, g_sq);
    cudaGetSymbolAddress((void**)&pidx, g_idx);

    k_stem<<<B * (N / 64), 256>>>(x, w_t1, g_t1, b_t1, w_t2, g_t2, b_t2, hA, psq);

    float* cur = hA;
    float* nxt = hB;
    for (int r = 0; r < R; r++) {
        k_knn<<<B * (N / 16), 256>>>(cur, psq, pidx);
        k_ac <<<NPTS / 64, 256>>>(cur, w_nb + (size_t)r * H * 2 * H, pa, pc);
        k_agg<<<NPTS / 8,  256>>>(pa, pc, pidx, g_nb + r * H, b_nb + r * H, nxt, psq);
        float* t = cur; cur = nxt; nxt = t;
    }

    k_head<<<NPTS / 64, 256>>>(cur, w_s1, g_s1, b_s1, w_s2, b_s2, out);
}

// round 10
// speedup vs baseline: 1.6160x; 1.0301x over previous
#include <cuda_runtime.h>
#include <float.h>
#include <math.h>

#define B 128
#define N 512
#define C 7
#define H 64
#define KNN 16
#define R 2
#define EPS 1e-5f
#define NPTS (B*N)

typedef unsigned long long u64;
typedef unsigned int u32;

// ---------------- scratch ----------------
__device__ float g_hA[NPTS * H];
__device__ float g_hB[NPTS * H];
__device__ float g_a [NPTS * H];
__device__ float g_c [NPTS * H];
__device__ float g_sq[NPTS];
__device__ int   g_idx[NPTS * KNN];

// packed f32x2 FMA (sm_100+): d = a*b + d elementwise on packed pairs
#define FMA2(d,a,b) asm("fma.rn.f32x2 %0, %1, %2, %3;" : "=l"(d) : "l"(a), "l"(b), "l"(d))

__device__ __forceinline__ void unpack2(u64 v, float& lo, float& hi) {
    asm("mov.b64 {%0,%1}, %2;" : "=f"(lo), "=f"(hi) : "l"(v));
}
__device__ __forceinline__ u64 pack2(float x, float y) {
    u64 r; asm("mov.b64 %0, {%1,%2};" : "=l"(r) : "f"(x), "f"(y)); return r;
}

// ============ stem: h = relu(bn(W2 relu(bn(W1 x)))), fused sq ============
__global__ __launch_bounds__(256,3) void k_stem(
    const float* __restrict__ x,
    const float* __restrict__ w1, const float* __restrict__ g1, const float* __restrict__ b1,
    const float* __restrict__ w2, const float* __restrict__ g2, const float* __restrict__ b2,
    float* __restrict__ out, float* __restrict__ sqout)
{
    __shared__ float xs [C * 68];
    __shared__ float w1t[C * 68];
    __shared__ float h1s[H * 68];
    __shared__ float w2t[H * 68];

    int tid = threadIdx.x;
    int b   = blockIdx.x >> 3;
    int n0  = (blockIdx.x & 7) << 6;

    for (int i = tid; i < C * 64; i += 256) {
        int c = i >> 6, p = i & 63;
        xs[c * 68 + p] = x[(size_t)b * C * N + c * N + n0 + p];
    }
    for (int i = tid; i < H * C; i += 256) {
        int o = i / 7, c = i - o * 7;
        w1t[c * 68 + o] = w1[i];
    }
    for (int i = tid; i < 1024; i += 256) {
        int o = i >> 4, c4 = (i & 15) << 2;
        float4 w = *(const float4*)&w2[o * 64 + c4];
        w2t[(c4+0) * 68 + o] = w.x; w2t[(c4+1) * 68 + o] = w.y;
        w2t[(c4+2) * 68 + o] = w.z; w2t[(c4+3) * 68 + o] = w.w;
    }
    __syncthreads();

    const float inv = 1.0f / sqrtf(1.0f + EPS);
    int po = (tid & 15) << 2, pp = (tid >> 4) << 2;

    {
        float acc[16];
        #pragma unroll
        for (int i = 0; i < 16; i++) acc[i] = 0.f;
        #pragma unroll
        for (int c = 0; c < C; c++) {
            float4 hv = *(const float4*)&xs [c * 68 + pp];
            float4 wv = *(const float4*)&w1t[c * 68 + po];
            float hh[4] = {hv.x, hv.y, hv.z, hv.w};
            float ww[4] = {wv.x, wv.y, wv.z, wv.w};
            #pragma unroll
            for (int i = 0; i < 4; i++)
                #pragma unroll
                for (int j = 0; j < 4; j++) acc[i*4+j] += hh[i] * ww[j];
        }
        float4 gg = *(const float4*)&g1[po];
        float4 bb = *(const float4*)&b1[po];
        float gs[4] = {gg.x*inv, gg.y*inv, gg.z*inv, gg.w*inv};
        float bs[4] = {bb.x, bb.y, bb.z, bb.w};
        #pragma unroll
        for (int i = 0; i < 4; i++)
            #pragma unroll
            for (int j = 0; j < 4; j++)
                h1s[(po+j) * 68 + pp + i] = fmaxf(acc[i*4+j] * gs[j] + bs[j], 0.f);
    }
    __syncthreads();

    {
        float acc[16];
        #pragma unroll
        for (int i = 0; i < 16; i++) acc[i] = 0.f;
        #pragma unroll 8
        for (int c = 0; c < H; c++) {
            float4 hv = *(const float4*)&h1s[c * 68 + pp];
            float4 wv = *(const float4*)&w2t[c * 68 + po];
            float hh[4] = {hv.x, hv.y, hv.z, hv.w};
            float ww[4] = {wv.x, wv.y, wv.z, wv.w};
            #pragma unroll
            for (int i = 0; i < 4; i++)
                #pragma unroll
                for (int j = 0; j < 4; j++) acc[i*4+j] += hh[i] * ww[j];
        }
        float4 gg = *(const float4*)&g2[po];
        float4 bb = *(const float4*)&b2[po];
        float gs[4] = {gg.x*inv, gg.y*inv, gg.z*inv, gg.w*inv};
        float bs[4] = {bb.x, bb.y, bb.z, bb.w};
        float sqv[4] = {0.f, 0.f, 0.f, 0.f};
        #pragma unroll
        for (int i = 0; i < 4; i++) {
            float v[4];
            #pragma unroll
            for (int j = 0; j < 4; j++) {
                v[j] = fmaxf(acc[i*4+j] * gs[j] + bs[j], 0.f);
                sqv[i] += v[j] * v[j];
            }
            float4 o4 = {v[0], v[1], v[2], v[3]};
            *(float4*)&out[((size_t)(b * N + n0 + pp + i)) * H + po] = o4;
        }
        #pragma unroll
        for (int i = 0; i < 4; i++) {
            #pragma unroll
            for (int off = 1; off < 16; off <<= 1)
                sqv[i] += __shfl_xor_sync(0xffffffffu, sqv[i], off);
        }
        if ((tid & 15) == 0) {
            #pragma unroll
            for (int i = 0; i < 4; i++)
                sqout[b * N + n0 + pp + i] = sqv[i];
        }
    }
}

// ============ fused distance-GEMM + exact top-16 ============
// block 256 thr (8 warps), 16 rows. GEMM: warp = 4 rows x half-columns
// (rg = warp>>1 row-group, hf = warp&1). Each hjs float4 feeds 4 rows.
// Then key exchange through smem; selection: warp = 2 rows (as before).
__global__ __launch_bounds__(256,2) void k_knn(
    const float* __restrict__ h, const float* __restrict__ sq, int* __restrict__ idxout)
{
    __shared__ float his[16 * 64];     // 4 KB
    __shared__ float4 tileF[2048];     // 32 KB: GEMM tile, then key[16][512], then spill
    __shared__ float sqs[512];         // 2 KB

    int b    = blockIdx.x >> 5;
    int i0   = (blockIdx.x & 31) << 4;
    int tid  = threadIdx.x;
    int lane = tid & 31;
    int warp = tid >> 5;
    int rg   = warp >> 1;              // row group 0..3 (4 rows each)
    int hf   = warp & 1;               // column half 0..1
    int r0   = rg << 2;
    int lmask = lane & 15;

    const float* hb = h + (size_t)b * N * H;
    u32* keybuf = (u32*)tileF;         // key[row][j] : 16*512 u32 = 32 KB

    for (int i = tid; i < 16 * 64; i += 256) his[i] = hb[(size_t)i0 * H + i];
    for (int i = tid; i < 512;     i += 256) sqs[i] = sq[b * N + i];

    // acc[r*8 + tile*2 + t] : r=0..3 rows, tile=0..3, t=0..1
    // j = tile*128 + hf*64 + t*32 + lane
    u64 acc[32];
    #pragma unroll
    for (int i = 0; i < 32; i++) acc[i] = 0ull;

    #pragma unroll
    for (int tile = 0; tile < 4; tile++) {
        __syncthreads();
        // fill swizzled at float4 granularity: chunk q of tile-row j at column (q ^ (j&15))
        for (int i = tid; i < 128 * 16; i += 256) {
            int j = i >> 4, q = i & 15;
            float4 v = *(const float4*)&hb[(size_t)((tile << 7) + j) * 64 + q * 4];
            tileF[j * 16 + (q ^ (j & 15))] = v;
        }
        __syncthreads();
        #pragma unroll 4
        for (int q = 0; q < 16; q++) {
            u64 alo[4], ahi[4];
            #pragma unroll
            for (int r = 0; r < 4; r++) {
                float4 av = *(const float4*)&his[(r0 + r) * 64 + q * 4];  // broadcast
                alo[r] = pack2(av.x, av.y); ahi[r] = pack2(av.z, av.w);
            }
            int qx = q ^ lmask;
            #pragma unroll
            for (int t = 0; t < 2; t++) {
                float4 bv = tileF[((hf << 6) + (t << 5) + lane) * 16 + qx];
                u64 blo = pack2(bv.x, bv.y), bhi = pack2(bv.z, bv.w);
                #pragma unroll
                for (int r = 0; r < 4; r++) {
                    FMA2(acc[r * 8 + tile * 2 + t], alo[r], blo);
                    FMA2(acc[r * 8 + tile * 2 + t], ahi[r], bhi);
                }
            }
        }
    }
    __syncthreads();   // GEMM tile reads done; tileF becomes key buffer

    // write monotone-u32 keys: key[row][j] = mono(sq[j] - 2*dot)   (bank = lane)
    #pragma unroll
    for (int r = 0; r < 4; r++) {
        #pragma unroll
        for (int tile = 0; tile < 4; tile++) {
            #pragma unroll
            for (int t = 0; t < 2; t++) {
                float lo, hi; unpack2(acc[r * 8 + tile * 2 + t], lo, hi);
                int j = (tile << 7) + (hf << 6) + (t << 5) + lane;
                float key = sqs[j] - 2.f * (lo + hi);
                u32 u = __float_as_uint(key);
                u = (u & 0x80000000u) ? ~u : (u | 0x80000000u);
                keybuf[(r0 + r) * 512 + j] = u;
            }
        }
    }
    __syncthreads();

    // selection: warp handles rows 2*warp, 2*warp+1; read both rows into regs FIRST,
    // then spill region = this warp's own two key rows (4 KB) — no cross-warp hazard.
    int lr0 = warp << 1;
    u64 sA[16], sB[16];
    #pragma unroll
    for (int t = 0; t < 16; t++) {
        int j = (t << 5) + lane;
        sA[t] = ((u64)keybuf[(lr0    ) * 512 + j] << 32) | (u32)j;
        sB[t] = ((u64)keybuf[(lr0 + 1) * 512 + j] << 32) | (u32)j;
    }
    u64* sreg = (u64*)(keybuf + lr0 * 512);   // 512 u64 = 4 KB, own rows

    #pragma unroll
    for (int rr = 0; rr < 2; rr++) {
        u64 s[16];
        #pragma unroll
        for (int t = 0; t < 16; t++) s[t] = rr ? sB[t] : sA[t];

        // bitonic sort 16 ascending (static indices)
        #pragma unroll
        for (int kk = 2; kk <= 16; kk <<= 1) {
            #pragma unroll
            for (int jj = kk >> 1; jj > 0; jj >>= 1) {
                #pragma unroll
                for (int i = 0; i < 16; i++) {
                    int l = i ^ jj;
                    if (l > i) {
                        bool dir = ((i & kk) == 0);
                        u64 x = s[i], y = s[l];
                        if ((x > y) == dir) { s[i] = y; s[l] = x; }
                    }
                }
            }
        }
        // spill sorted lists transposed: bank = lane -> conflict-free at any head
        #pragma unroll
        for (int i = 0; i < 16; i++) sreg[i * 32 + lane] = s[i];
        __syncwarp();

        size_t rowbase = ((size_t)(b * N + i0 + lr0 + rr)) * KNN;
        u32 khi = (u32)(s[0] >> 32);
        u32 klo = (u32)s[0];
        int hidx = 0;
        #pragma unroll 1
        for (int k = 0; k < KNN; k++) {
            u32 mh = __reduce_min_sync(0xffffffffu, khi);
            u32 cand = (khi == mh) ? klo : 0xffffffffu;
            u32 mj = __reduce_min_sync(0xffffffffu, cand);
            if (lane == 0) idxout[rowbase + k] = (int)mj;
            bool own = (khi == mh) && (klo == mj);
            hidx += own;
            int hc = hidx < 15 ? hidx : 15;
            u64 nv = sreg[hc * 32 + lane];
            if (own) {
                if (hidx < 16) { khi = (u32)(nv >> 32); klo = (u32)nv; }
                else           { khi = 0xffffffffu;     klo = 0xffffffffu; }
            }
        }
        __syncwarp();
    }
}

// ============ a = (Wa-Wb) h ; c = Wb h ============
__global__ __launch_bounds__(256,3) void k_ac(
    const float* __restrict__ h, const float* __restrict__ wnb,
    float* __restrict__ a, float* __restrict__ c)
{
    __shared__ float hs[H * 68];
    __shared__ float wt[H * 68];

    int tid = threadIdx.x;
    int p0g = blockIdx.x << 6;

    for (int i = tid; i < 1024; i += 256) {
        int p = i >> 4, c4 = (i & 15) << 2;
        float4 v = *(const float4*)&h[(size_t)(p0g + p) * H + c4];
        hs[(c4+0) * 68 + p] = v.x; hs[(c4+1) * 68 + p] = v.y;
        hs[(c4+2) * 68 + p] = v.z; hs[(c4+3) * 68 + p] = v.w;
    }

    int po = (tid & 15) << 2, pp = (tid >> 4) << 2;

    #pragma unroll
    for (int m = 0; m < 2; m++) {
        __syncthreads();
        for (int i = tid; i < 1024; i += 256) {
            int o = i >> 4, c4 = (i & 15) << 2;
            float4 wb = *(const float4*)&wnb[o * 128 + 64 + c4];
            if (m == 0) {
                float4 wa = *(const float4*)&wnb[o * 128 + c4];
                wt[(c4+0) * 68 + o] = wa.x - wb.x; wt[(c4+1) * 68 + o] = wa.y - wb.y;
                wt[(c4+2) * 68 + o] = wa.z - wb.z; wt[(c4+3) * 68 + o] = wa.w - wb.w;
            } else {
                wt[(c4+0) * 68 + o] = wb.x; wt[(c4+1) * 68 + o] = wb.y;
                wt[(c4+2) * 68 + o] = wb.z; wt[(c4+3) * 68 + o] = wb.w;
            }
        }
        __syncthreads();

        float facc[16];
        #pragma unroll
        for (int i = 0; i < 16; i++) facc[i] = 0.f;
        #pragma unroll 8
        for (int cc = 0; cc < H; cc++) {
            float4 hv = *(const float4*)&hs[cc * 68 + pp];
            float4 wv = *(const float4*)&wt[cc * 68 + po];
            float hh[4] = {hv.x, hv.y, hv.z, hv.w};
            float ww[4] = {wv.x, wv.y, wv.z, wv.w};
            #pragma unroll
            for (int i = 0; i < 4; i++)
                #pragma unroll
                for (int j = 0; j < 4; j++) facc[i*4+j] += hh[i] * ww[j];
        }
        float* dst = (m == 0) ? a : c;
        #pragma unroll
        for (int i = 0; i < 4; i++) {
            float4 o4 = {facc[i*4+0], facc[i*4+1], facc[i*4+2], facc[i*4+3]};
            *(float4*)&dst[(size_t)(p0g + pp + i) * H + po] = o4;
        }
    }
}

// ============ aggregate + bn + relu + fused sq ============
__global__ __launch_bounds__(256) void k_agg(
    const float* __restrict__ a, const float* __restrict__ c,
    const int* __restrict__ knn,
    const float* __restrict__ g, const float* __restrict__ bb,
    float* __restrict__ hout, float* __restrict__ sqout)
{
    int p    = blockIdx.x * 8 + (threadIdx.x >> 5);
    int lane = threadIdx.x & 31;
    int b    = p / N;
    const float2* cb = (const float2*)(c + (size_t)b * N * H);
    const int*    kn = knn + (size_t)p * KNN;

    float mx0 = -FLT_MAX, mx1 = -FLT_MAX, mn0 = FLT_MAX, mn1 = FLT_MAX;
    #pragma unroll
    for (int k = 0; k < KNN; k++) {
        int j = kn[k];
        float2 v = cb[(size_t)j * 32 + lane];
        mx0 = fmaxf(mx0, v.x); mn0 = fminf(mn0, v.x);
        mx1 = fmaxf(mx1, v.y); mn1 = fminf(mn1, v.y);
    }
    float2 av = ((const float2*)a)[(size_t)p * 32 + lane];
    float2 g2 = ((const float2*)g)[lane];
    float2 b2 = ((const float2*)bb)[lane];
    const float inv = 1.0f / sqrtf(1.0f + EPS);
    float s0 = g2.x * inv, s1 = g2.y * inv;
    float e0 = (s0 >= 0.f) ? mx0 : mn0;
    float e1 = (s1 >= 0.f) ? mx1 : mn1;
    float o0 = fmaxf(s0 * (av.x + e0) + b2.x, 0.f);
    float o1 = fmaxf(s1 * (av.y + e1) + b2.y, 0.f);
    float2 o2 = {o0, o1};
    ((float2*)hout)[(size_t)p * 32 + lane] = o2;

    float sv = o0 * o0 + o1 * o1;
    #pragma unroll
    for (int off = 16; off; off >>= 1) sv += __shfl_xor_sync(0xffffffffu, sv, off);
    if (lane == 0) sqout[p] = sv;
}

// ============ head ============
__global__ __launch_bounds__(256,3) void k_head(
    const float* __restrict__ h,
    const float* __restrict__ ws1, const float* __restrict__ g1, const float* __restrict__ b1,
    const float* __restrict__ ws2, const float* __restrict__ b2,
    float* __restrict__ out)
{
    __shared__ float hs[H * 68];
    __shared__ float wt[H * 68];

    int tid = threadIdx.x;
    int p0g = blockIdx.x << 6;

    for (int i = tid; i < 1024; i += 256) {
        int p = i >> 4, c4 = (i & 15) << 2;
        float4 v = *(const float4*)&h[(size_t)(p0g + p) * H + c4];
        hs[(c4+0) * 68 + p] = v.x; hs[(c4+1) * 68 + p] = v.y;
        hs[(c4+2) * 68 + p] = v.z; hs[(c4+3) * 68 + p] = v.w;
    }
    for (int i = tid; i < 1024; i += 256) {
        int o = i >> 4, c4 = (i & 15) << 2;
        float4 w = *(const float4*)&ws1[o * 64 + c4];
        wt[(c4+0) * 68 + o] = w.x; wt[(c4+1) * 68 + o] = w.y;
        wt[(c4+2) * 68 + o] = w.z; wt[(c4+3) * 68 + o] = w.w;
    }
    __syncthreads();

    const float inv = 1.0f / sqrtf(1.0f + EPS);
    int po = (tid & 15) << 2, pp = (tid >> 4) << 2;

    float acc[16];
    #pragma unroll
    for (int i = 0; i < 16; i++) acc[i] = 0.f;
    #pragma unroll 8
    for (int cc = 0; cc < H; cc++) {
        float4 hv = *(const float4*)&hs[cc * 68 + pp];
        float4 wv = *(const float4*)&wt[cc * 68 + po];
        float hh[4] = {hv.x, hv.y, hv.z, hv.w};
        float ww[4] = {wv.x, wv.y, wv.z, wv.w};
        #pragma unroll
        for (int i = 0; i < 4; i++)
            #pragma unroll
            for (int j = 0; j < 4; j++) acc[i*4+j] += hh[i] * ww[j];
    }
    float4 gg = *(const float4*)&g1[po];
    float4 bv = *(const float4*)&b1[po];
    float gs[4] = {gg.x*inv, gg.y*inv, gg.z*inv, gg.w*inv};
    float bs[4] = {bv.x, bv.y, bv.z, bv.w};
    __syncthreads();
    #pragma unroll
    for (int i = 0; i < 4; i++)
        #pragma unroll
        for (int j = 0; j < 4; j++)
            hs[(pp + i) * 68 + po + j] = fmaxf(acc[i*4+j] * gs[j] + bs[j], 0.f);
    __syncthreads();

    int lane = tid & 31, warp = tid >> 5;
    float w0 = ws2[lane], w1 = ws2[32 + lane];
    #pragma unroll
    for (int i = 0; i < 8; i++) {
        int pi = warp * 8 + i;
        float v = hs[pi * 68 + lane] * w0 + hs[pi * 68 + 32 + lane] * w1;
        #pragma unroll
        for (int off = 16; off; off >>= 1) v += __shfl_xor_sync(0xffffffffu, v, off);
        if (lane == 0) out[p0g + pi] = v + b2[0];
    }
}

// ---------------- launch ----------------
extern "C" void kernel_launch(void* const* d_in, const int* in_sizes, int n_in,
                              void* d_out, int out_size)
{
    const float* x    = (const float*)d_in[0];
    const float* w_t1 = (const float*)d_in[1];
    const float* g_t1 = (const float*)d_in[2];
    const float* b_t1 = (const float*)d_in[3];
    const float* w_t2 = (const float*)d_in[4];
    const float* g_t2 = (const float*)d_in[5];
    const float* b_t2 = (const float*)d_in[6];
    const float* w_nb = (const float*)d_in[7];
    const float* g_nb = (const float*)d_in[8];
    const float* b_nb = (const float*)d_in[9];
    const float* w_s1 = (const float*)d_in[10];
    const float* g_s1 = (const float*)d_in[11];
    const float* b_s1 = (const float*)d_in[12];
    const float* w_s2 = (const float*)d_in[13];
    const float* b_s2 = (const float*)d_in[14];
    float* out = (float*)d_out;

    float *hA, *hB, *pa, *pc, *psq; int* pidx;
    cudaGetSymbolAddress((void**)&hA,  g_hA);
    cudaGetSymbolAddress((void**)&hB,  g_hB);
    cudaGetSymbolAddress((void**)&pa,  g_a);
    cudaGetSymbolAddress((void**)&pc,  g_c);
    cudaGetSymbolAddress((void**)&psq, g_sq);
    cudaGetSymbolAddress((void**)&pidx, g_idx);

    k_stem<<<B * (N / 64), 256>>>(x, w_t1, g_t1, b_t1, w_t2, g_t2, b_t2, hA, psq);

    float* cur = hA;
    float* nxt = hB;
    for (int r = 0; r < R; r++) {
        k_knn<<<B * (N / 16), 256>>>(cur, psq, pidx);
        k_ac <<<NPTS / 64, 256>>>(cur, w_nb + (size_t)r * H * 2 * H, pa, pc);
        k_agg<<<NPTS / 8,  256>>>(pa, pc, pidx, g_nb + r * H, b_nb + r * H, nxt, psq);
        float* t = cur; cur = nxt; nxt = t;
    }

    k_head<<<NPTS / 64, 256>>>(cur, w_s1, g_s1, b_s1, w_s2, b_s2, out);
}